// round 10
// baseline (speedup 1.0000x reference)
#include <cuda_runtime.h>
#include <cuda_bf16.h>
#include <math.h>

#define NN 50000
#define EE 800000
#define ET (EE + NN)
#define HC 64
#define F_IN 128
#define OUTD 16
#define NBIN 256

__device__ __align__(16) float g_xl[(size_t)NN * HC];
__device__ __align__(16) float g_xr[(size_t)NN * HC];
__device__ __align__(16) float g_h [(size_t)NN * HC];
__device__ __align__(16) float g_agg[(size_t)NN * HC];
__device__ int g_csrsrc[(size_t)ET];
__device__ int g_start[NN];
__device__ int g_cnt[NN];
__device__ int g_cur[NN];
__device__ int g_perm[NN];
__device__ int g_hist[NBIN];
__device__ int g_binofs[NBIN];
__device__ int g_cursor;
__device__ int g_is64;

// ---------------------------------------------------------------------------
__global__ void k_detect(const int* __restrict__ ei) {
    if (threadIdx.x == 0 && blockIdx.x == 0) {
        int is64 = 1;
        for (int i = 0; i < 256; i++)
            if (ei[2 * i + 1] != 0) { is64 = 0; break; }
        g_is64 = is64;
    }
}

__global__ void k_reset() {
    int n = blockIdx.x * blockDim.x + threadIdx.x;
    if (n < NN) g_cnt[n] = 0;
    if (n < NBIN) g_hist[n] = 0;
    if (n == 0) g_cursor = 0;
}

__device__ __forceinline__ int edge_dst(const int* ei, int e) {
    if (e >= EE) return e - EE;
    return g_is64 ? (int)((const long long*)ei)[(size_t)EE + e] : ei[EE + e];
}
__device__ __forceinline__ int edge_src(const int* ei, int e) {
    if (e >= EE) return e - EE;
    return g_is64 ? (int)((const long long*)ei)[e] : ei[e];
}

__global__ void k_count(const int* __restrict__ ei) {
    int e = blockIdx.x * blockDim.x + threadIdx.x;
    if (e >= ET) return;
    atomicAdd(&g_cnt[edge_dst(ei, e)], 1);
}

// warp-aggregated ticket allocation of CSR row starts + degree histogram
__global__ void k_alloc() {
    int n = blockIdx.x * blockDim.x + threadIdx.x;
    int lane = threadIdx.x & 31;
    int c = (n < NN) ? g_cnt[n] : 0;
    int s = c;
    #pragma unroll
    for (int o = 1; o < 32; o <<= 1) {
        int v = __shfl_up_sync(0xffffffffu, s, o);
        if (lane >= o) s += v;
    }
    int total = __shfl_sync(0xffffffffu, s, 31);
    int base = 0;
    if (lane == 31) base = atomicAdd(&g_cursor, total);
    base = __shfl_sync(0xffffffffu, base, 31);
    if (n < NN) {
        int st = base + s - c;
        g_start[n] = st;
        g_cur[n] = st;
        atomicAdd(&g_hist[c < NBIN ? c : NBIN - 1], 1);
    }
}

// one-block exclusive scan of the degree histogram
__global__ void k_prefix() {
    __shared__ int sh[NBIN];
    int t = threadIdx.x;
    sh[t] = g_hist[t];
    __syncthreads();
    int v = sh[t];
    #pragma unroll
    for (int o = 1; o < NBIN; o <<= 1) {
        int u = (t >= o) ? sh[t - o] : 0;
        __syncthreads();
        sh[t] = v = v + u;
        __syncthreads();
    }
    g_binofs[t] = v - g_hist[t];   // exclusive
}

// scatter node ids into degree-sorted order
__global__ void k_place() {
    int n = blockIdx.x * blockDim.x + threadIdx.x;
    if (n >= NN) return;
    int c = g_cnt[n];
    int b = c < NBIN ? c : NBIN - 1;
    int pos = atomicAdd(&g_binofs[b], 1);
    g_perm[pos] = n;
}

__global__ void k_scatter(const int* __restrict__ ei) {
    int e = blockIdx.x * blockDim.x + threadIdx.x;
    if (e >= ET) return;
    int s = edge_src(ei, e);
    int d = edge_dst(ei, e);
    int pos = atomicAdd(&g_cur[d], 1);
    g_csrsrc[pos] = s;
}

// ---------------------------------------------------------------------------
// Fused dual SGEMM: outL = X @ Wl + bl, outR = X @ Wr + br (shared A tile).
// BM=64, BN=64, BK=16, 256 threads, TM=TN=4.
template <int KT>
__global__ void __launch_bounds__(256, 3)
k_gemm_fused(const float* __restrict__ X,
             const float* __restrict__ Wl, const float* __restrict__ bl,
             const float* __restrict__ Wr, const float* __restrict__ br,
             float* __restrict__ outL, float* __restrict__ outR) {
    __shared__ float As[16][68];
    __shared__ float WsL[16][64];
    __shared__ float WsR[16][64];

    const int tid = threadIdx.x;
    const int m0 = blockIdx.x * 64;
    const int tx = tid & 15;
    const int ty = tid >> 4;

    float accL[4][4] = {};
    float accR[4][4] = {};

    for (int kc = 0; kc < KT; kc += 16) {
        {
            int r  = tid >> 2;
            int c4 = tid & 3;
            int m  = m0 + r;
            float4 v = make_float4(0.f, 0.f, 0.f, 0.f);
            if (m < NN) v = *(const float4*)(X + (size_t)m * KT + kc + c4 * 4);
            As[c4 * 4 + 0][r] = v.x;
            As[c4 * 4 + 1][r] = v.y;
            As[c4 * 4 + 2][r] = v.z;
            As[c4 * 4 + 3][r] = v.w;
        }
        {
            int k  = tid >> 4;
            int c4 = tid & 15;
            *(float4*)&WsL[k][c4 * 4] = *(const float4*)(Wl + (size_t)(kc + k) * 64 + c4 * 4);
            *(float4*)&WsR[k][c4 * 4] = *(const float4*)(Wr + (size_t)(kc + k) * 64 + c4 * 4);
        }
        __syncthreads();
        #pragma unroll
        for (int kk = 0; kk < 16; kk++) {
            float a[4], bL[4], bR[4];
            *(float4*)a  = *(const float4*)&As[kk][ty * 4];
            *(float4*)bL = *(const float4*)&WsL[kk][tx * 4];
            *(float4*)bR = *(const float4*)&WsR[kk][tx * 4];
            #pragma unroll
            for (int i = 0; i < 4; i++)
                #pragma unroll
                for (int j = 0; j < 4; j++) {
                    accL[i][j] += a[i] * bL[j];
                    accR[i][j] += a[i] * bR[j];
                }
        }
        __syncthreads();
    }

    float4 bvL = *(const float4*)(bl + tx * 4);
    float4 bvR = *(const float4*)(br + tx * 4);
    #pragma unroll
    for (int i = 0; i < 4; i++) {
        int m = m0 + ty * 4 + i;
        if (m < NN) {
            float4 r;
            r.x = accL[i][0] + bvL.x; r.y = accL[i][1] + bvL.y;
            r.z = accL[i][2] + bvL.z; r.w = accL[i][3] + bvL.w;
            *(float4*)(outL + (size_t)m * 64 + tx * 4) = r;
            r.x = accR[i][0] + bvR.x; r.y = accR[i][1] + bvR.y;
            r.z = accR[i][2] + bvR.z; r.w = accR[i][3] + bvR.w;
            *(float4*)(outR + (size_t)m * 64 + tx * 4) = r;
        }
    }
}

// ---------------------------------------------------------------------------
// CSR edge pass, degree-sorted, 2-edge ILP. 16 lanes per destination node.
// LAYER 0: h = relu(v + b1) -> g_h. LAYER 1: v -> g_agg.
template <int LAYER>
__global__ void k_edge_csr(const float* __restrict__ att,
                           const float* __restrict__ bias) {
    int t = blockIdx.x * blockDim.x + threadIdx.x;
    int idx = t >> 4;
    int g = t & 15;
    if (idx >= NN) return;
    int n = g_perm[idx];

    const int beg = g_start[n];
    const int cnt = g_cnt[n];
    const int lane = threadIdx.x & 31;
    const unsigned mask8 = 0xffu << (lane & 24);   // 8-lane head subgroup

    float4 xr4 = *(const float4*)(g_xr + (size_t)n * 64 + g * 4);
    int head = g >> 3;
    float4 a4 = *(const float4*)(att + head * 32 + (g & 7) * 4);

    float acc0 = 0.f, acc1 = 0.f, acc2 = 0.f, acc3 = 0.f, dn = 0.f;

    int i = 0;
    for (; i + 2 <= cnt; i += 2) {
        int s0 = __ldg(&g_csrsrc[beg + i]);
        int s1 = __ldg(&g_csrsrc[beg + i + 1]);
        float4 x0 = __ldg((const float4*)(g_xl + (size_t)s0 * 64 + g * 4));
        float4 x1 = __ldg((const float4*)(g_xl + (size_t)s1 * 64 + g * 4));

        float u0 = x0.x + xr4.x, u1 = x0.y + xr4.y, u2 = x0.z + xr4.z, u3 = x0.w + xr4.w;
        float w0 = x1.x + xr4.x, w1 = x1.y + xr4.y, w2 = x1.z + xr4.z, w3 = x1.w + xr4.w;
        u0 = u0 > 0.f ? u0 : 0.2f * u0;  w0 = w0 > 0.f ? w0 : 0.2f * w0;
        u1 = u1 > 0.f ? u1 : 0.2f * u1;  w1 = w1 > 0.f ? w1 : 0.2f * w1;
        u2 = u2 > 0.f ? u2 : 0.2f * u2;  w2 = w2 > 0.f ? w2 : 0.2f * w2;
        u3 = u3 > 0.f ? u3 : 0.2f * u3;  w3 = w3 > 0.f ? w3 : 0.2f * w3;
        float p0 = u0 * a4.x + u1 * a4.y + u2 * a4.z + u3 * a4.w;
        float p1 = w0 * a4.x + w1 * a4.y + w2 * a4.z + w3 * a4.w;
        p0 += __shfl_xor_sync(mask8, p0, 1);
        p1 += __shfl_xor_sync(mask8, p1, 1);
        p0 += __shfl_xor_sync(mask8, p0, 2);
        p1 += __shfl_xor_sync(mask8, p1, 2);
        p0 += __shfl_xor_sync(mask8, p0, 4);
        p1 += __shfl_xor_sync(mask8, p1, 4);
        float e0 = __expf(p0);
        float e1 = __expf(p1);
        dn += e0 + e1;
        acc0 += e0 * x0.x + e1 * x1.x;
        acc1 += e0 * x0.y + e1 * x1.y;
        acc2 += e0 * x0.z + e1 * x1.z;
        acc3 += e0 * x0.w + e1 * x1.w;
    }
    if (i < cnt) {
        int s0 = __ldg(&g_csrsrc[beg + i]);
        float4 x0 = __ldg((const float4*)(g_xl + (size_t)s0 * 64 + g * 4));
        float u0 = x0.x + xr4.x, u1 = x0.y + xr4.y, u2 = x0.z + xr4.z, u3 = x0.w + xr4.w;
        u0 = u0 > 0.f ? u0 : 0.2f * u0;
        u1 = u1 > 0.f ? u1 : 0.2f * u1;
        u2 = u2 > 0.f ? u2 : 0.2f * u2;
        u3 = u3 > 0.f ? u3 : 0.2f * u3;
        float p0 = u0 * a4.x + u1 * a4.y + u2 * a4.z + u3 * a4.w;
        p0 += __shfl_xor_sync(mask8, p0, 1);
        p0 += __shfl_xor_sync(mask8, p0, 2);
        p0 += __shfl_xor_sync(mask8, p0, 4);
        float e0 = __expf(p0);
        dn += e0;
        acc0 += e0 * x0.x;
        acc1 += e0 * x0.y;
        acc2 += e0 * x0.z;
        acc3 += e0 * x0.w;
    }

    float r = 1.f / dn;
    int c = g * 4;
    float4 v;
    v.x = acc0 * r; v.y = acc1 * r; v.z = acc2 * r; v.w = acc3 * r;
    if (LAYER == 0) {
        v.x += bias[c + 0]; v.y += bias[c + 1];
        v.z += bias[c + 2]; v.w += bias[c + 3];
        v.x = v.x > 0.f ? v.x : 0.f;
        v.y = v.y > 0.f ? v.y : 0.f;
        v.z = v.z > 0.f ? v.z : 0.f;
        v.w = v.w > 0.f ? v.w : 0.f;
        *(float4*)(g_h + (size_t)n * 64 + c) = v;
    } else {
        *(float4*)(g_agg + (size_t)n * 64 + c) = v;
    }
}

// ---------------------------------------------------------------------------
// Final head: b2 + BN + relu -> emb (Wp,bp) -> risk. Thread per node.
__global__ void k_final(const float* __restrict__ b2,
                        const float* __restrict__ bn_g, const float* __restrict__ bn_b,
                        const float* __restrict__ bn_m, const float* __restrict__ bn_v,
                        const float* __restrict__ Wp, const float* __restrict__ bp,
                        const float* __restrict__ Wh1, const float* __restrict__ bh1,
                        const float* __restrict__ Wh2, const float* __restrict__ bh2,
                        float* __restrict__ out) {
    int n = blockIdx.x * blockDim.x + threadIdx.x;
    if (n >= NN) return;

    float h[64];
    #pragma unroll
    for (int i = 0; i < 64; i++) {
        float v = g_agg[(size_t)n * 64 + i] + b2[i];
        v = (v - bn_m[i]) * rsqrtf(bn_v[i] + 1e-5f) * bn_g[i] + bn_b[i];
        h[i] = v > 0.f ? v : 0.f;
    }
    float emb[16];
    #pragma unroll
    for (int j = 0; j < 16; j++) emb[j] = bp[j];
    #pragma unroll
    for (int k = 0; k < 64; k++) {
        float hk = h[k];
        #pragma unroll
        for (int j = 0; j < 16; j++) emb[j] += hk * Wp[k * 16 + j];
    }
    #pragma unroll
    for (int j = 0; j < 16; j++) out[(size_t)n * 16 + j] = emb[j];

    float hid[8];
    #pragma unroll
    for (int j = 0; j < 8; j++) {
        float s = bh1[j];
        #pragma unroll
        for (int k = 0; k < 16; k++) s += emb[k] * Wh1[k * 8 + j];
        hid[j] = s > 0.f ? s : 0.f;
    }
    float risk = bh2[0];
    #pragma unroll
    for (int j = 0; j < 8; j++) risk += hid[j] * Wh2[j];
    out[(size_t)NN * 16 + n] = risk;
}

// ---------------------------------------------------------------------------
extern "C" void kernel_launch(void* const* d_in, const int* in_sizes, int n_in,
                              void* d_out, int out_size) {
    const float* x    = (const float*)d_in[0];
    const int*   ei   = (const int*)d_in[1];
    const float* Wl1  = (const float*)d_in[2];
    const float* bl1  = (const float*)d_in[3];
    const float* Wr1  = (const float*)d_in[4];
    const float* br1  = (const float*)d_in[5];
    const float* att1 = (const float*)d_in[6];
    const float* b1   = (const float*)d_in[7];
    const float* Wl2  = (const float*)d_in[8];
    const float* bl2  = (const float*)d_in[9];
    const float* Wr2  = (const float*)d_in[10];
    const float* br2  = (const float*)d_in[11];
    const float* att2 = (const float*)d_in[12];
    const float* b2   = (const float*)d_in[13];
    const float* bn_g = (const float*)d_in[14];
    const float* bn_b = (const float*)d_in[15];
    const float* bn_m = (const float*)d_in[16];
    const float* bn_v = (const float*)d_in[17];
    const float* Wp   = (const float*)d_in[18];
    const float* bp   = (const float*)d_in[19];
    const float* Wh1  = (const float*)d_in[20];
    const float* bh1  = (const float*)d_in[21];
    const float* Wh2  = (const float*)d_in[22];
    const float* bh2  = (const float*)d_in[23];
    float* out = (float*)d_out;

    float *p_xl, *p_xr, *p_h;
    cudaGetSymbolAddress((void**)&p_xl, g_xl);
    cudaGetSymbolAddress((void**)&p_xr, g_xr);
    cudaGetSymbolAddress((void**)&p_h,  g_h);

    const int RB = (NN + 255) / 256;
    const int CB = (ET + 255) / 256;
    const int GB = (NN + 63) / 64;
    const int NB = (NN * 16 + 255) / 256;

    k_detect<<<1, 32>>>(ei);
    k_reset<<<RB, 256>>>();
    k_count<<<CB, 256>>>(ei);
    k_alloc<<<RB, 256>>>();
    k_prefix<<<1, NBIN>>>();
    k_place<<<RB, 256>>>();
    k_scatter<<<CB, 256>>>(ei);
    k_gemm_fused<F_IN><<<GB, 256>>>(x, Wl1, bl1, Wr1, br1, p_xl, p_xr);
    k_edge_csr<0><<<NB, 256>>>(att1, b1);
    k_gemm_fused<HC><<<GB, 256>>>(p_h, Wl2, bl2, Wr2, br2, p_xl, p_xr);
    k_edge_csr<1><<<NB, 256>>>(att2, nullptr);
    k_final<<<(NN + 127) / 128, 128>>>(b2, bn_g, bn_b, bn_m, bn_v,
                                       Wp, bp, Wh1, bh1, Wh2, bh2, out);
}

// round 12
// speedup vs baseline: 1.0569x; 1.0569x over previous
#include <cuda_runtime.h>
#include <cuda_bf16.h>
#include <math.h>

#define NN 50000
#define EE 800000
#define ET (EE + NN)
#define HC 64
#define F_IN 128
#define OUTD 16

__device__ __align__(16) float g_xl[(size_t)NN * HC];
__device__ __align__(16) float g_xr[(size_t)NN * HC];
__device__ __align__(16) float g_h [(size_t)NN * HC];
__device__ __align__(16) float g_agg[(size_t)NN * HC];
__device__ int g_csrsrc[(size_t)ET];
__device__ int g_start[NN];
__device__ int g_cnt[NN];
__device__ int g_cur[NN];
__device__ int g_cursor;
__device__ int g_is64;

// ---------------------------------------------------------------------------
__global__ void k_detect(const int* __restrict__ ei) {
    if (threadIdx.x == 0 && blockIdx.x == 0) {
        int is64 = 1;
        for (int i = 0; i < 256; i++)
            if (ei[2 * i + 1] != 0) { is64 = 0; break; }
        g_is64 = is64;
    }
}

__global__ void k_reset() {
    int n = blockIdx.x * blockDim.x + threadIdx.x;
    if (n < NN) g_cnt[n] = 0;
    if (n == 0) g_cursor = 0;
}

__device__ __forceinline__ int edge_dst(const int* ei, int e) {
    if (e >= EE) return e - EE;
    return g_is64 ? (int)((const long long*)ei)[(size_t)EE + e] : ei[EE + e];
}
__device__ __forceinline__ int edge_src(const int* ei, int e) {
    if (e >= EE) return e - EE;
    return g_is64 ? (int)((const long long*)ei)[e] : ei[e];
}

__global__ void k_count(const int* __restrict__ ei) {
    int e = blockIdx.x * blockDim.x + threadIdx.x;
    if (e >= ET) return;
    atomicAdd(&g_cnt[edge_dst(ei, e)], 1);
}

// warp-aggregated ticket allocation of CSR row starts
__global__ void k_alloc() {
    int n = blockIdx.x * blockDim.x + threadIdx.x;
    int lane = threadIdx.x & 31;
    int c = (n < NN) ? g_cnt[n] : 0;
    int s = c;
    #pragma unroll
    for (int o = 1; o < 32; o <<= 1) {
        int v = __shfl_up_sync(0xffffffffu, s, o);
        if (lane >= o) s += v;
    }
    int total = __shfl_sync(0xffffffffu, s, 31);
    int base = 0;
    if (lane == 31) base = atomicAdd(&g_cursor, total);
    base = __shfl_sync(0xffffffffu, base, 31);
    if (n < NN) {
        int st = base + s - c;
        g_start[n] = st;
        g_cur[n] = st;
    }
}

__global__ void k_scatter(const int* __restrict__ ei) {
    int e = blockIdx.x * blockDim.x + threadIdx.x;
    if (e >= ET) return;
    int s = edge_src(ei, e);
    int d = edge_dst(ei, e);
    int pos = atomicAdd(&g_cur[d], 1);
    g_csrsrc[pos] = s;
}

// ---------------------------------------------------------------------------
// Fused dual SGEMM: outL = X @ Wl + bl, outR = X @ Wr + br (shared A tile).
// BM=64, BN=64, BK=16, 256 threads, TM=TN=4.
template <int KT>
__global__ void __launch_bounds__(256, 3)
k_gemm_fused(const float* __restrict__ X,
             const float* __restrict__ Wl, const float* __restrict__ bl,
             const float* __restrict__ Wr, const float* __restrict__ br,
             float* __restrict__ outL, float* __restrict__ outR) {
    __shared__ float As[16][68];
    __shared__ float WsL[16][64];
    __shared__ float WsR[16][64];

    const int tid = threadIdx.x;
    const int m0 = blockIdx.x * 64;
    const int tx = tid & 15;
    const int ty = tid >> 4;

    float accL[4][4] = {};
    float accR[4][4] = {};

    for (int kc = 0; kc < KT; kc += 16) {
        {
            int r  = tid >> 2;
            int c4 = tid & 3;
            int m  = m0 + r;
            float4 v = make_float4(0.f, 0.f, 0.f, 0.f);
            if (m < NN) v = *(const float4*)(X + (size_t)m * KT + kc + c4 * 4);
            As[c4 * 4 + 0][r] = v.x;
            As[c4 * 4 + 1][r] = v.y;
            As[c4 * 4 + 2][r] = v.z;
            As[c4 * 4 + 3][r] = v.w;
        }
        {
            int k  = tid >> 4;
            int c4 = tid & 15;
            *(float4*)&WsL[k][c4 * 4] = *(const float4*)(Wl + (size_t)(kc + k) * 64 + c4 * 4);
            *(float4*)&WsR[k][c4 * 4] = *(const float4*)(Wr + (size_t)(kc + k) * 64 + c4 * 4);
        }
        __syncthreads();
        #pragma unroll
        for (int kk = 0; kk < 16; kk++) {
            float a[4], bL[4], bR[4];
            *(float4*)a  = *(const float4*)&As[kk][ty * 4];
            *(float4*)bL = *(const float4*)&WsL[kk][tx * 4];
            *(float4*)bR = *(const float4*)&WsR[kk][tx * 4];
            #pragma unroll
            for (int i = 0; i < 4; i++)
                #pragma unroll
                for (int j = 0; j < 4; j++) {
                    accL[i][j] += a[i] * bL[j];
                    accR[i][j] += a[i] * bR[j];
                }
        }
        __syncthreads();
    }

    float4 bvL = *(const float4*)(bl + tx * 4);
    float4 bvR = *(const float4*)(br + tx * 4);
    #pragma unroll
    for (int i = 0; i < 4; i++) {
        int m = m0 + ty * 4 + i;
        if (m < NN) {
            float4 r;
            r.x = accL[i][0] + bvL.x; r.y = accL[i][1] + bvL.y;
            r.z = accL[i][2] + bvL.z; r.w = accL[i][3] + bvL.w;
            *(float4*)(outL + (size_t)m * 64 + tx * 4) = r;
            r.x = accR[i][0] + bvR.x; r.y = accR[i][1] + bvR.y;
            r.z = accR[i][2] + bvR.z; r.w = accR[i][3] + bvR.w;
            *(float4*)(outR + (size_t)m * 64 + tx * 4) = r;
        }
    }
}

// ---------------------------------------------------------------------------
// CSR edge pass, 4-edge ILP. 16 lanes per destination node (node-ordered).
// LAYER 0: h = relu(v + b1) -> g_h. LAYER 1: v -> g_agg.
template <int LAYER>
__global__ void k_edge_csr(const float* __restrict__ att,
                           const float* __restrict__ bias) {
    int t = blockIdx.x * blockDim.x + threadIdx.x;
    int n = t >> 4;
    int g = t & 15;
    if (n >= NN) return;

    const int beg = g_start[n];
    const int cnt = g_cnt[n];
    const int lane = threadIdx.x & 31;
    const unsigned mask8 = 0xffu << (lane & 24);   // 8-lane head subgroup

    float4 xr4 = *(const float4*)(g_xr + (size_t)n * 64 + g * 4);
    int head = g >> 3;
    float4 a4 = *(const float4*)(att + head * 32 + (g & 7) * 4);

    float acc0 = 0.f, acc1 = 0.f, acc2 = 0.f, acc3 = 0.f, dn = 0.f;

    int i = 0;
    for (; i + 4 <= cnt; i += 4) {
        int s0 = __ldg(&g_csrsrc[beg + i]);
        int s1 = __ldg(&g_csrsrc[beg + i + 1]);
        int s2 = __ldg(&g_csrsrc[beg + i + 2]);
        int s3 = __ldg(&g_csrsrc[beg + i + 3]);
        float4 x0 = __ldg((const float4*)(g_xl + (size_t)s0 * 64 + g * 4));
        float4 x1 = __ldg((const float4*)(g_xl + (size_t)s1 * 64 + g * 4));
        float4 x2 = __ldg((const float4*)(g_xl + (size_t)s2 * 64 + g * 4));
        float4 x3 = __ldg((const float4*)(g_xl + (size_t)s3 * 64 + g * 4));

        float p0, p1, p2, p3;
        {
            float u0 = x0.x + xr4.x, u1 = x0.y + xr4.y, u2 = x0.z + xr4.z, u3 = x0.w + xr4.w;
            u0 = u0 > 0.f ? u0 : 0.2f * u0;  u1 = u1 > 0.f ? u1 : 0.2f * u1;
            u2 = u2 > 0.f ? u2 : 0.2f * u2;  u3 = u3 > 0.f ? u3 : 0.2f * u3;
            p0 = u0 * a4.x + u1 * a4.y + u2 * a4.z + u3 * a4.w;
        }
        {
            float u0 = x1.x + xr4.x, u1 = x1.y + xr4.y, u2 = x1.z + xr4.z, u3 = x1.w + xr4.w;
            u0 = u0 > 0.f ? u0 : 0.2f * u0;  u1 = u1 > 0.f ? u1 : 0.2f * u1;
            u2 = u2 > 0.f ? u2 : 0.2f * u2;  u3 = u3 > 0.f ? u3 : 0.2f * u3;
            p1 = u0 * a4.x + u1 * a4.y + u2 * a4.z + u3 * a4.w;
        }
        {
            float u0 = x2.x + xr4.x, u1 = x2.y + xr4.y, u2 = x2.z + xr4.z, u3 = x2.w + xr4.w;
            u0 = u0 > 0.f ? u0 : 0.2f * u0;  u1 = u1 > 0.f ? u1 : 0.2f * u1;
            u2 = u2 > 0.f ? u2 : 0.2f * u2;  u3 = u3 > 0.f ? u3 : 0.2f * u3;
            p2 = u0 * a4.x + u1 * a4.y + u2 * a4.z + u3 * a4.w;
        }
        {
            float u0 = x3.x + xr4.x, u1 = x3.y + xr4.y, u2 = x3.z + xr4.z, u3 = x3.w + xr4.w;
            u0 = u0 > 0.f ? u0 : 0.2f * u0;  u1 = u1 > 0.f ? u1 : 0.2f * u1;
            u2 = u2 > 0.f ? u2 : 0.2f * u2;  u3 = u3 > 0.f ? u3 : 0.2f * u3;
            p3 = u0 * a4.x + u1 * a4.y + u2 * a4.z + u3 * a4.w;
        }
        p0 += __shfl_xor_sync(mask8, p0, 1);
        p1 += __shfl_xor_sync(mask8, p1, 1);
        p2 += __shfl_xor_sync(mask8, p2, 1);
        p3 += __shfl_xor_sync(mask8, p3, 1);
        p0 += __shfl_xor_sync(mask8, p0, 2);
        p1 += __shfl_xor_sync(mask8, p1, 2);
        p2 += __shfl_xor_sync(mask8, p2, 2);
        p3 += __shfl_xor_sync(mask8, p3, 2);
        p0 += __shfl_xor_sync(mask8, p0, 4);
        p1 += __shfl_xor_sync(mask8, p1, 4);
        p2 += __shfl_xor_sync(mask8, p2, 4);
        p3 += __shfl_xor_sync(mask8, p3, 4);
        float e0 = __expf(p0);
        float e1 = __expf(p1);
        float e2 = __expf(p2);
        float e3 = __expf(p3);
        dn += (e0 + e1) + (e2 + e3);
        acc0 += e0 * x0.x + e1 * x1.x + e2 * x2.x + e3 * x3.x;
        acc1 += e0 * x0.y + e1 * x1.y + e2 * x2.y + e3 * x3.y;
        acc2 += e0 * x0.z + e1 * x1.z + e2 * x2.z + e3 * x3.z;
        acc3 += e0 * x0.w + e1 * x1.w + e2 * x2.w + e3 * x3.w;
    }
    for (; i < cnt; i++) {
        int s0 = __ldg(&g_csrsrc[beg + i]);
        float4 x0 = __ldg((const float4*)(g_xl + (size_t)s0 * 64 + g * 4));
        float u0 = x0.x + xr4.x, u1 = x0.y + xr4.y, u2 = x0.z + xr4.z, u3 = x0.w + xr4.w;
        u0 = u0 > 0.f ? u0 : 0.2f * u0;
        u1 = u1 > 0.f ? u1 : 0.2f * u1;
        u2 = u2 > 0.f ? u2 : 0.2f * u2;
        u3 = u3 > 0.f ? u3 : 0.2f * u3;
        float p0 = u0 * a4.x + u1 * a4.y + u2 * a4.z + u3 * a4.w;
        p0 += __shfl_xor_sync(mask8, p0, 1);
        p0 += __shfl_xor_sync(mask8, p0, 2);
        p0 += __shfl_xor_sync(mask8, p0, 4);
        float e0 = __expf(p0);
        dn += e0;
        acc0 += e0 * x0.x;
        acc1 += e0 * x0.y;
        acc2 += e0 * x0.z;
        acc3 += e0 * x0.w;
    }

    float r = 1.f / dn;
    int c = g * 4;
    float4 v;
    v.x = acc0 * r; v.y = acc1 * r; v.z = acc2 * r; v.w = acc3 * r;
    if (LAYER == 0) {
        v.x += bias[c + 0]; v.y += bias[c + 1];
        v.z += bias[c + 2]; v.w += bias[c + 3];
        v.x = v.x > 0.f ? v.x : 0.f;
        v.y = v.y > 0.f ? v.y : 0.f;
        v.z = v.z > 0.f ? v.z : 0.f;
        v.w = v.w > 0.f ? v.w : 0.f;
        *(float4*)(g_h + (size_t)n * 64 + c) = v;
    } else {
        *(float4*)(g_agg + (size_t)n * 64 + c) = v;
    }
}

// ---------------------------------------------------------------------------
// Final head: b2 + BN + relu -> emb (Wp,bp) -> risk. Thread per node.
__global__ void k_final(const float* __restrict__ b2,
                        const float* __restrict__ bn_g, const float* __restrict__ bn_b,
                        const float* __restrict__ bn_m, const float* __restrict__ bn_v,
                        const float* __restrict__ Wp, const float* __restrict__ bp,
                        const float* __restrict__ Wh1, const float* __restrict__ bh1,
                        const float* __restrict__ Wh2, const float* __restrict__ bh2,
                        float* __restrict__ out) {
    int n = blockIdx.x * blockDim.x + threadIdx.x;
    if (n >= NN) return;

    float h[64];
    #pragma unroll
    for (int i = 0; i < 64; i++) {
        float v = g_agg[(size_t)n * 64 + i] + b2[i];
        v = (v - bn_m[i]) * rsqrtf(bn_v[i] + 1e-5f) * bn_g[i] + bn_b[i];
        h[i] = v > 0.f ? v : 0.f;
    }
    float emb[16];
    #pragma unroll
    for (int j = 0; j < 16; j++) emb[j] = bp[j];
    #pragma unroll
    for (int k = 0; k < 64; k++) {
        float hk = h[k];
        #pragma unroll
        for (int j = 0; j < 16; j++) emb[j] += hk * Wp[k * 16 + j];
    }
    #pragma unroll
    for (int j = 0; j < 16; j++) out[(size_t)n * 16 + j] = emb[j];

    float hid[8];
    #pragma unroll
    for (int j = 0; j < 8; j++) {
        float s = bh1[j];
        #pragma unroll
        for (int k = 0; k < 16; k++) s += emb[k] * Wh1[k * 8 + j];
        hid[j] = s > 0.f ? s : 0.f;
    }
    float risk = bh2[0];
    #pragma unroll
    for (int j = 0; j < 8; j++) risk += hid[j] * Wh2[j];
    out[(size_t)NN * 16 + n] = risk;
}

// ---------------------------------------------------------------------------
extern "C" void kernel_launch(void* const* d_in, const int* in_sizes, int n_in,
                              void* d_out, int out_size) {
    const float* x    = (const float*)d_in[0];
    const int*   ei   = (const int*)d_in[1];
    const float* Wl1  = (const float*)d_in[2];
    const float* bl1  = (const float*)d_in[3];
    const float* Wr1  = (const float*)d_in[4];
    const float* br1  = (const float*)d_in[5];
    const float* att1 = (const float*)d_in[6];
    const float* b1   = (const float*)d_in[7];
    const float* Wl2  = (const float*)d_in[8];
    const float* bl2  = (const float*)d_in[9];
    const float* Wr2  = (const float*)d_in[10];
    const float* br2  = (const float*)d_in[11];
    const float* att2 = (const float*)d_in[12];
    const float* b2   = (const float*)d_in[13];
    const float* bn_g = (const float*)d_in[14];
    const float* bn_b = (const float*)d_in[15];
    const float* bn_m = (const float*)d_in[16];
    const float* bn_v = (const float*)d_in[17];
    const float* Wp   = (const float*)d_in[18];
    const float* bp   = (const float*)d_in[19];
    const float* Wh1  = (const float*)d_in[20];
    const float* bh1  = (const float*)d_in[21];
    const float* Wh2  = (const float*)d_in[22];
    const float* bh2  = (const float*)d_in[23];
    float* out = (float*)d_out;

    float *p_xl, *p_xr, *p_h;
    cudaGetSymbolAddress((void**)&p_xl, g_xl);
    cudaGetSymbolAddress((void**)&p_xr, g_xr);
    cudaGetSymbolAddress((void**)&p_h,  g_h);

    const int RB = (NN + 255) / 256;
    const int CB = (ET + 255) / 256;
    const int GB = (NN + 63) / 64;
    const int NB = (NN * 16 + 255) / 256;

    k_detect<<<1, 32>>>(ei);
    k_reset<<<RB, 256>>>();
    k_count<<<CB, 256>>>(ei);
    k_alloc<<<RB, 256>>>();
    k_scatter<<<CB, 256>>>(ei);
    k_gemm_fused<F_IN><<<GB, 256>>>(x, Wl1, bl1, Wr1, br1, p_xl, p_xr);
    k_edge_csr<0><<<NB, 256>>>(att1, b1);
    k_gemm_fused<HC><<<GB, 256>>>(p_h, Wl2, bl2, Wr2, br2, p_xl, p_xr);
    k_edge_csr<1><<<NB, 256>>>(att2, nullptr);
    k_final<<<(NN + 127) / 128, 128>>>(b2, bn_g, bn_b, bn_m, bn_v,
                                       Wp, bp, Wh1, bh1, Wh2, bh2, out);
}

// round 13
// speedup vs baseline: 1.0753x; 1.0174x over previous
#include <cuda_runtime.h>
#include <cuda_bf16.h>
#include <math.h>

#define NN 50000
#define EE 800000
#define ET (EE + NN)
#define HC 64
#define F_IN 128
#define OUTD 16

__device__ __align__(16) float g_xl[(size_t)NN * HC];
__device__ __align__(16) float g_xr[(size_t)NN * HC];
__device__ __align__(16) float g_h [(size_t)NN * HC];
__device__ __align__(16) float g_agg[(size_t)NN * HC];
__device__ int g_csrsrc[(size_t)ET];
__device__ int g_start[NN];
__device__ int g_cnt[NN];
__device__ int g_cur[NN];
__device__ int g_cursor;
__device__ int g_is64;

// ---------------------------------------------------------------------------
// reset + dtype detect (merged: keeps edge<0> at ncu capture slot #6)
__global__ void k_reset(const int* __restrict__ ei) {
    int n = blockIdx.x * blockDim.x + threadIdx.x;
    if (n < NN) g_cnt[n] = 0;
    if (n == 0) {
        g_cursor = 0;
        int is64 = 1;
        for (int i = 0; i < 256; i++)
            if (ei[2 * i + 1] != 0) { is64 = 0; break; }
        g_is64 = is64;
    }
}

__device__ __forceinline__ int edge_dst(const int* ei, int e) {
    if (e >= EE) return e - EE;
    return g_is64 ? (int)((const long long*)ei)[(size_t)EE + e] : ei[EE + e];
}
__device__ __forceinline__ int edge_src(const int* ei, int e) {
    if (e >= EE) return e - EE;
    return g_is64 ? (int)((const long long*)ei)[e] : ei[e];
}

__global__ void k_count(const int* __restrict__ ei) {
    int e = blockIdx.x * blockDim.x + threadIdx.x;
    if (e >= ET) return;
    atomicAdd(&g_cnt[edge_dst(ei, e)], 1);
}

// warp-aggregated ticket allocation of CSR row starts
__global__ void k_alloc() {
    int n = blockIdx.x * blockDim.x + threadIdx.x;
    int lane = threadIdx.x & 31;
    int c = (n < NN) ? g_cnt[n] : 0;
    int s = c;
    #pragma unroll
    for (int o = 1; o < 32; o <<= 1) {
        int v = __shfl_up_sync(0xffffffffu, s, o);
        if (lane >= o) s += v;
    }
    int total = __shfl_sync(0xffffffffu, s, 31);
    int base = 0;
    if (lane == 31) base = atomicAdd(&g_cursor, total);
    base = __shfl_sync(0xffffffffu, base, 31);
    if (n < NN) {
        int st = base + s - c;
        g_start[n] = st;
        g_cur[n] = st;
    }
}

__global__ void k_scatter(const int* __restrict__ ei) {
    int e = blockIdx.x * blockDim.x + threadIdx.x;
    if (e >= ET) return;
    int s = edge_src(ei, e);
    int d = edge_dst(ei, e);
    int pos = atomicAdd(&g_cur[d], 1);
    g_csrsrc[pos] = s;
}

// ---------------------------------------------------------------------------
// Fused dual SGEMM: outL = X @ Wl + bl, outR = X @ Wr + br (shared A tile).
// BM=64, BN=64, BK=16, 256 threads, TM=TN=4.
template <int KT>
__global__ void __launch_bounds__(256, 3)
k_gemm_fused(const float* __restrict__ X,
             const float* __restrict__ Wl, const float* __restrict__ bl,
             const float* __restrict__ Wr, const float* __restrict__ br,
             float* __restrict__ outL, float* __restrict__ outR) {
    __shared__ float As[16][68];
    __shared__ float WsL[16][64];
    __shared__ float WsR[16][64];

    const int tid = threadIdx.x;
    const int m0 = blockIdx.x * 64;
    const int tx = tid & 15;
    const int ty = tid >> 4;

    float accL[4][4] = {};
    float accR[4][4] = {};

    for (int kc = 0; kc < KT; kc += 16) {
        {
            int r  = tid >> 2;
            int c4 = tid & 3;
            int m  = m0 + r;
            float4 v = make_float4(0.f, 0.f, 0.f, 0.f);
            if (m < NN) v = *(const float4*)(X + (size_t)m * KT + kc + c4 * 4);
            As[c4 * 4 + 0][r] = v.x;
            As[c4 * 4 + 1][r] = v.y;
            As[c4 * 4 + 2][r] = v.z;
            As[c4 * 4 + 3][r] = v.w;
        }
        {
            int k  = tid >> 4;
            int c4 = tid & 15;
            *(float4*)&WsL[k][c4 * 4] = *(const float4*)(Wl + (size_t)(kc + k) * 64 + c4 * 4);
            *(float4*)&WsR[k][c4 * 4] = *(const float4*)(Wr + (size_t)(kc + k) * 64 + c4 * 4);
        }
        __syncthreads();
        #pragma unroll
        for (int kk = 0; kk < 16; kk++) {
            float a[4], bL[4], bR[4];
            *(float4*)a  = *(const float4*)&As[kk][ty * 4];
            *(float4*)bL = *(const float4*)&WsL[kk][tx * 4];
            *(float4*)bR = *(const float4*)&WsR[kk][tx * 4];
            #pragma unroll
            for (int i = 0; i < 4; i++)
                #pragma unroll
                for (int j = 0; j < 4; j++) {
                    accL[i][j] += a[i] * bL[j];
                    accR[i][j] += a[i] * bR[j];
                }
        }
        __syncthreads();
    }

    float4 bvL = *(const float4*)(bl + tx * 4);
    float4 bvR = *(const float4*)(br + tx * 4);
    #pragma unroll
    for (int i = 0; i < 4; i++) {
        int m = m0 + ty * 4 + i;
        if (m < NN) {
            float4 r;
            r.x = accL[i][0] + bvL.x; r.y = accL[i][1] + bvL.y;
            r.z = accL[i][2] + bvL.z; r.w = accL[i][3] + bvL.w;
            *(float4*)(outL + (size_t)m * 64 + tx * 4) = r;
            r.x = accR[i][0] + bvR.x; r.y = accR[i][1] + bvR.y;
            r.z = accR[i][2] + bvR.z; r.w = accR[i][3] + bvR.w;
            *(float4*)(outR + (size_t)m * 64 + tx * 4) = r;
        }
    }
}

// ---------------------------------------------------------------------------
// CSR edge pass: one WARP per destination node. Two 16-lane slots process two
// edges concurrently (zero cross-node divergence), x2 unroll = 4 gathers in
// flight. Cross-half combine via shfl_xor(16) at the end.
// LAYER 0: h = relu(v + b1) -> g_h. LAYER 1: v -> g_agg.
template <int LAYER>
__global__ void k_edge_csr(const float* __restrict__ att,
                           const float* __restrict__ bias) {
    int t = blockIdx.x * blockDim.x + threadIdx.x;
    int n = t >> 5;                     // warp per node
    if (n >= NN) return;
    const int lane = threadIdx.x & 31;
    const int sub = lane >> 4;          // edge slot 0/1
    const int g = lane & 15;            // feature group within node
    const unsigned mask8 = 0xffu << (lane & 24);   // 8-lane head subgroup

    const int beg = g_start[n];
    const int cnt = g_cnt[n];

    float4 xr4 = *(const float4*)(g_xr + (size_t)n * 64 + g * 4);
    int head = (lane >> 3) & 1;
    float4 a4 = *(const float4*)(att + head * 32 + (g & 7) * 4);

    float acc0 = 0.f, acc1 = 0.f, acc2 = 0.f, acc3 = 0.f, dn = 0.f;

    int i = 0;
    for (; i + 4 <= cnt; i += 4) {
        int sA = __ldg(&g_csrsrc[beg + i + sub]);
        int sB = __ldg(&g_csrsrc[beg + i + 2 + sub]);
        float4 xA = __ldg((const float4*)(g_xl + (size_t)sA * 64 + g * 4));
        float4 xB = __ldg((const float4*)(g_xl + (size_t)sB * 64 + g * 4));

        float pA, pB;
        {
            float u0 = xA.x + xr4.x, u1 = xA.y + xr4.y, u2 = xA.z + xr4.z, u3 = xA.w + xr4.w;
            u0 = u0 > 0.f ? u0 : 0.2f * u0;  u1 = u1 > 0.f ? u1 : 0.2f * u1;
            u2 = u2 > 0.f ? u2 : 0.2f * u2;  u3 = u3 > 0.f ? u3 : 0.2f * u3;
            pA = u0 * a4.x + u1 * a4.y + u2 * a4.z + u3 * a4.w;
        }
        {
            float u0 = xB.x + xr4.x, u1 = xB.y + xr4.y, u2 = xB.z + xr4.z, u3 = xB.w + xr4.w;
            u0 = u0 > 0.f ? u0 : 0.2f * u0;  u1 = u1 > 0.f ? u1 : 0.2f * u1;
            u2 = u2 > 0.f ? u2 : 0.2f * u2;  u3 = u3 > 0.f ? u3 : 0.2f * u3;
            pB = u0 * a4.x + u1 * a4.y + u2 * a4.z + u3 * a4.w;
        }
        pA += __shfl_xor_sync(mask8, pA, 1);
        pB += __shfl_xor_sync(mask8, pB, 1);
        pA += __shfl_xor_sync(mask8, pA, 2);
        pB += __shfl_xor_sync(mask8, pB, 2);
        pA += __shfl_xor_sync(mask8, pA, 4);
        pB += __shfl_xor_sync(mask8, pB, 4);
        float eA = __expf(pA);
        float eB = __expf(pB);
        dn += eA + eB;
        acc0 += eA * xA.x + eB * xB.x;
        acc1 += eA * xA.y + eB * xB.y;
        acc2 += eA * xA.z + eB * xB.z;
        acc3 += eA * xA.w + eB * xB.w;
    }
    if (i + 2 <= cnt) {                 // 2 more edges (one per slot)
        int sA = __ldg(&g_csrsrc[beg + i + sub]);
        float4 xA = __ldg((const float4*)(g_xl + (size_t)sA * 64 + g * 4));
        float u0 = xA.x + xr4.x, u1 = xA.y + xr4.y, u2 = xA.z + xr4.z, u3 = xA.w + xr4.w;
        u0 = u0 > 0.f ? u0 : 0.2f * u0;  u1 = u1 > 0.f ? u1 : 0.2f * u1;
        u2 = u2 > 0.f ? u2 : 0.2f * u2;  u3 = u3 > 0.f ? u3 : 0.2f * u3;
        float pA = u0 * a4.x + u1 * a4.y + u2 * a4.z + u3 * a4.w;
        pA += __shfl_xor_sync(mask8, pA, 1);
        pA += __shfl_xor_sync(mask8, pA, 2);
        pA += __shfl_xor_sync(mask8, pA, 4);
        float eA = __expf(pA);
        dn += eA;
        acc0 += eA * xA.x; acc1 += eA * xA.y;
        acc2 += eA * xA.z; acc3 += eA * xA.w;
        i += 2;
    }
    if (i < cnt && sub == 0) {          // last odd edge: slot 0 only
        int sA = __ldg(&g_csrsrc[beg + i]);
        float4 xA = __ldg((const float4*)(g_xl + (size_t)sA * 64 + g * 4));
        float u0 = xA.x + xr4.x, u1 = xA.y + xr4.y, u2 = xA.z + xr4.z, u3 = xA.w + xr4.w;
        u0 = u0 > 0.f ? u0 : 0.2f * u0;  u1 = u1 > 0.f ? u1 : 0.2f * u1;
        u2 = u2 > 0.f ? u2 : 0.2f * u2;  u3 = u3 > 0.f ? u3 : 0.2f * u3;
        float pA = u0 * a4.x + u1 * a4.y + u2 * a4.z + u3 * a4.w;
        pA += __shfl_xor_sync(mask8, pA, 1);
        pA += __shfl_xor_sync(mask8, pA, 2);
        pA += __shfl_xor_sync(mask8, pA, 4);
        float eA = __expf(pA);
        dn += eA;
        acc0 += eA * xA.x; acc1 += eA * xA.y;
        acc2 += eA * xA.z; acc3 += eA * xA.w;
    }

    // combine the two 16-lane halves
    acc0 += __shfl_xor_sync(0xffffffffu, acc0, 16);
    acc1 += __shfl_xor_sync(0xffffffffu, acc1, 16);
    acc2 += __shfl_xor_sync(0xffffffffu, acc2, 16);
    acc3 += __shfl_xor_sync(0xffffffffu, acc3, 16);
    dn   += __shfl_xor_sync(0xffffffffu, dn, 16);

    if (sub == 0) {
        float r = 1.f / dn;
        int c = g * 4;
        float4 v;
        v.x = acc0 * r; v.y = acc1 * r; v.z = acc2 * r; v.w = acc3 * r;
        if (LAYER == 0) {
            v.x += bias[c + 0]; v.y += bias[c + 1];
            v.z += bias[c + 2]; v.w += bias[c + 3];
            v.x = v.x > 0.f ? v.x : 0.f;
            v.y = v.y > 0.f ? v.y : 0.f;
            v.z = v.z > 0.f ? v.z : 0.f;
            v.w = v.w > 0.f ? v.w : 0.f;
            *(float4*)(g_h + (size_t)n * 64 + c) = v;
        } else {
            *(float4*)(g_agg + (size_t)n * 64 + c) = v;
        }
    }
}

// ---------------------------------------------------------------------------
// Final head: b2 + BN + relu -> emb (Wp,bp) -> risk. Thread per node.
__global__ void k_final(const float* __restrict__ b2,
                        const float* __restrict__ bn_g, const float* __restrict__ bn_b,
                        const float* __restrict__ bn_m, const float* __restrict__ bn_v,
                        const float* __restrict__ Wp, const float* __restrict__ bp,
                        const float* __restrict__ Wh1, const float* __restrict__ bh1,
                        const float* __restrict__ Wh2, const float* __restrict__ bh2,
                        float* __restrict__ out) {
    int n = blockIdx.x * blockDim.x + threadIdx.x;
    if (n >= NN) return;

    float h[64];
    #pragma unroll
    for (int i = 0; i < 64; i++) {
        float v = g_agg[(size_t)n * 64 + i] + b2[i];
        v = (v - bn_m[i]) * rsqrtf(bn_v[i] + 1e-5f) * bn_g[i] + bn_b[i];
        h[i] = v > 0.f ? v : 0.f;
    }
    float emb[16];
    #pragma unroll
    for (int j = 0; j < 16; j++) emb[j] = bp[j];
    #pragma unroll
    for (int k = 0; k < 64; k++) {
        float hk = h[k];
        #pragma unroll
        for (int j = 0; j < 16; j++) emb[j] += hk * Wp[k * 16 + j];
    }
    #pragma unroll
    for (int j = 0; j < 16; j++) out[(size_t)n * 16 + j] = emb[j];

    float hid[8];
    #pragma unroll
    for (int j = 0; j < 8; j++) {
        float s = bh1[j];
        #pragma unroll
        for (int k = 0; k < 16; k++) s += emb[k] * Wh1[k * 8 + j];
        hid[j] = s > 0.f ? s : 0.f;
    }
    float risk = bh2[0];
    #pragma unroll
    for (int j = 0; j < 8; j++) risk += hid[j] * Wh2[j];
    out[(size_t)NN * 16 + n] = risk;
}

// ---------------------------------------------------------------------------
extern "C" void kernel_launch(void* const* d_in, const int* in_sizes, int n_in,
                              void* d_out, int out_size) {
    const float* x    = (const float*)d_in[0];
    const int*   ei   = (const int*)d_in[1];
    const float* Wl1  = (const float*)d_in[2];
    const float* bl1  = (const float*)d_in[3];
    const float* Wr1  = (const float*)d_in[4];
    const float* br1  = (const float*)d_in[5];
    const float* att1 = (const float*)d_in[6];
    const float* b1   = (const float*)d_in[7];
    const float* Wl2  = (const float*)d_in[8];
    const float* bl2  = (const float*)d_in[9];
    const float* Wr2  = (const float*)d_in[10];
    const float* br2  = (const float*)d_in[11];
    const float* att2 = (const float*)d_in[12];
    const float* b2   = (const float*)d_in[13];
    const float* bn_g = (const float*)d_in[14];
    const float* bn_b = (const float*)d_in[15];
    const float* bn_m = (const float*)d_in[16];
    const float* bn_v = (const float*)d_in[17];
    const float* Wp   = (const float*)d_in[18];
    const float* bp   = (const float*)d_in[19];
    const float* Wh1  = (const float*)d_in[20];
    const float* bh1  = (const float*)d_in[21];
    const float* Wh2  = (const float*)d_in[22];
    const float* bh2  = (const float*)d_in[23];
    float* out = (float*)d_out;

    float *p_xl, *p_xr, *p_h;
    cudaGetSymbolAddress((void**)&p_xl, g_xl);
    cudaGetSymbolAddress((void**)&p_xr, g_xr);
    cudaGetSymbolAddress((void**)&p_h,  g_h);

    const int RB = (NN + 255) / 256;
    const int CB = (ET + 255) / 256;
    const int GB = (NN + 63) / 64;
    const int WB = (NN * 32 + 255) / 256;

    k_reset<<<RB, 256>>>(ei);
    k_count<<<CB, 256>>>(ei);
    k_alloc<<<RB, 256>>>();
    k_scatter<<<CB, 256>>>(ei);
    k_gemm_fused<F_IN><<<GB, 256>>>(x, Wl1, bl1, Wr1, br1, p_xl, p_xr);
    k_edge_csr<0><<<WB, 256>>>(att1, b1);   // launch #6: ncu capture slot
    k_gemm_fused<HC><<<GB, 256>>>(p_h, Wl2, bl2, Wr2, br2, p_xl, p_xr);
    k_edge_csr<1><<<WB, 256>>>(att2, nullptr);
    k_final<<<(NN + 127) / 128, 128>>>(b2, bn_g, bn_b, bn_m, bn_v,
                                       Wp, bp, Wh1, bh1, Wh2, bh2, out);
}